// round 1
// baseline (speedup 1.0000x reference)
#include <cuda_runtime.h>
#include <cstdint>
#include <cmath>

#define ND    1000
#define FIN   2048
#define DD    128
#define NPRO  20000
#define LAMBD 1e-6f
#define SK    4        // split-K for MLP1

typedef unsigned long long ull;

// ---------------- device scratch (no allocations allowed) ----------------
__device__ __align__(16) float g_h1[ND * DD];     // MLP1 pre-activation (split-K accum)
__device__ __align__(16) float g_h [ND * DD];     // drug embedding after MLP2
__device__ __align__(16) float g_agg[ND * DD];    // segment sum (only dst < ND matters)
__device__ __align__(16) float g_cnt[ND];
__device__ __align__(16) float g_fx [ND * DD];    // finalX
__device__ __align__(16) float g_w2s[DD * 512];   // outW2 gathered columns
__device__ __align__(16) float g_b2s[512];

// ---------------- helpers ----------------
__device__ __forceinline__ float hshrink(float v) {
    return (fabsf(v) > LAMBD) ? v : 0.0f;
}
__device__ __forceinline__ ull dup2(float a) {
    ull r; asm("mov.b64 %0, {%1,%1};" : "=l"(r) : "f"(a)); return r;
}
__device__ __forceinline__ void fma2(ull& d, ull a, ull b) {
    asm("fma.rn.f32x2 %0, %1, %2, %0;" : "+l"(d) : "l"(a), "l"(b));
}
__device__ __forceinline__ float2 unpack2(ull v) {
    float2 f; asm("mov.b64 {%0,%1}, %2;" : "=f"(f.x), "=f"(f.y) : "l"(v)); return f;
}

// ---------------- K0: zero scratch ----------------
__global__ void k_zero() {
    int i = blockIdx.x * 256 + threadIdx.x;
    if (i < ND * DD) { g_h1[i] = 0.0f; g_agg[i] = 0.0f; }
    if (i < ND) g_cnt[i] = 0.0f;
}

// ---------------- K1: h1 = drugF @ W1  (split-K, atomic accumulate) ----------------
__global__ void k_mlp1(const float* __restrict__ dF, const float* __restrict__ W1) {
    __shared__ float As[16][33];
    __shared__ float Bs[32][128];
    const int rb = blockIdx.x * 16;
    const int k0 = blockIdx.y * (FIN / SK);
    const int t  = threadIdx.x;
    const int c  = t & 127, rg = t >> 7;     // rg in {0,1}: rows rg*8 .. rg*8+7

    float acc[8];
#pragma unroll
    for (int r = 0; r < 8; r++) acc[r] = 0.0f;

    for (int kb = 0; kb < FIN / SK; kb += 32) {
        {   // load A tile 16x32
            int kk = t & 31, r = t >> 5;
#pragma unroll
            for (int i = 0; i < 2; i++) {
                int rr = r + i * 8;
                int grow = rb + rr;
                As[rr][kk] = (grow < ND) ? dF[(size_t)grow * FIN + k0 + kb + kk] : 0.0f;
            }
        }
        {   // load B tile 32x128
#pragma unroll
            for (int i = 0; i < 16; i++) {
                int lin = t + i * 256;
                int kk = lin >> 7, cc = lin & 127;
                Bs[kk][cc] = W1[(size_t)(k0 + kb + kk) * DD + cc];
            }
        }
        __syncthreads();
#pragma unroll 8
        for (int kk = 0; kk < 32; kk++) {
            float b = Bs[kk][c];
#pragma unroll
            for (int rr = 0; rr < 8; rr++)
                acc[rr] += As[rg * 8 + rr][kk] * b;
        }
        __syncthreads();
    }
#pragma unroll
    for (int rr = 0; rr < 8; rr++) {
        int grow = rb + rg * 8 + rr;
        if (grow < ND) atomicAdd(&g_h1[grow * DD + c], acc[rr]);
    }
}

// ---------------- K2: h = relu(relu(h1+b1) @ W2 + b2) ----------------
__global__ void k_mlp2(const float* __restrict__ W2, const float* __restrict__ b1,
                       const float* __restrict__ b2) {
    __shared__ float hs[8][128];
    const int rb = blockIdx.x * 8;
    const int t  = threadIdx.x;
#pragma unroll
    for (int i = 0; i < 4; i++) {
        int lin = t + i * 256;
        int r = lin >> 7, cc = lin & 127;
        hs[r][cc] = fmaxf(g_h1[(rb + r) * DD + cc] + b1[cc], 0.0f);
    }
    __syncthreads();
    const int c = t & 127, rg = t >> 7;
    float acc[4];
#pragma unroll
    for (int rr = 0; rr < 4; rr++) acc[rr] = b2[c];
#pragma unroll 4
    for (int k = 0; k < 128; k++) {
        float w = W2[k * DD + c];
#pragma unroll
        for (int rr = 0; rr < 4; rr++)
            acc[rr] += hs[rg * 4 + rr][k] * w;
    }
#pragma unroll
    for (int rr = 0; rr < 4; rr++)
        g_h[(rb + rg * 4 + rr) * DD + c] = fmaxf(acc[rr], 0.0f);
}

// ---------------- K3: edge aggregation (only dst < ND matters) ----------------
__global__ void k_agg(const int* __restrict__ ei, const float* __restrict__ pe, int E) {
    const int e = blockIdx.x * 256 + threadIdx.x;
    const int lane = threadIdx.x & 31;
    int dst = 0, src = 0;
    bool act = false;
    if (e < E) {
        dst = ei[E + e];
        act = (dst < ND);
        if (act) src = ei[e];
    }
    unsigned m = __ballot_sync(0xffffffffu, act);
    while (m) {
        int leader = __ffs(m) - 1;
        m &= m - 1;
        int d = __shfl_sync(0xffffffffu, dst, leader);
        int s = __shfl_sync(0xffffffffu, src, leader);
        const float4* p = (s < ND) ? (const float4*)(g_h + s * DD)
                                   : (const float4*)(pe + (size_t)(s - ND) * DD);
        float4 v = p[lane];
        float* ap = g_agg + d * DD + lane * 4;
        asm volatile("red.global.add.v4.f32 [%0], {%1,%2,%3,%4};"
                     :: "l"(ap), "f"(v.x), "f"(v.y), "f"(v.z), "f"(v.w) : "memory");
        if (lane == 0) atomicAdd(&g_cnt[d], 1.0f);
    }
}

// ---------------- K4a: gather selected outW2 columns ----------------
__global__ void k_sel(const float* __restrict__ oW2, const float* __restrict__ oB2,
                      const int* __restrict__ ses, int S, int nSe) {
    int idx = blockIdx.x * 256 + threadIdx.x;
    if (idx < DD * S) {
        int k = idx / S, j = idx - k * S;
        g_w2s[k * S + j] = oW2[(size_t)k * nSe + ses[j]];
    }
    if (idx < S) g_b2s[idx] = oB2[ses[idx]];
}

// ---------------- K4b: finalX = relu(mean @ Wl + bl + h @ Wr) ----------------
__global__ void k_sage(const float* __restrict__ Wl, const float* __restrict__ bl,
                       const float* __restrict__ Wr) {
    __shared__ float ms[8][128];
    __shared__ float hs[8][128];
    const int rb = blockIdx.x * 8;
    const int t  = threadIdx.x;
#pragma unroll
    for (int i = 0; i < 4; i++) {
        int lin = t + i * 256;
        int r = lin >> 7, cc = lin & 127;
        float cnt = fmaxf(g_cnt[rb + r], 1.0f);
        ms[r][cc] = g_agg[(rb + r) * DD + cc] / cnt;
        hs[r][cc] = g_h[(rb + r) * DD + cc];
    }
    __syncthreads();
    const int c = t & 127, rg = t >> 7;
    float acc[4];
#pragma unroll
    for (int rr = 0; rr < 4; rr++) acc[rr] = bl[c];
#pragma unroll 4
    for (int k = 0; k < 128; k++) {
        float wl = Wl[k * DD + c];
        float wr = Wr[k * DD + c];
#pragma unroll
        for (int rr = 0; rr < 4; rr++)
            acc[rr] += ms[rg * 4 + rr][k] * wl + hs[rg * 4 + rr][k] * wr;
    }
#pragma unroll
    for (int rr = 0; rr < 4; rr++)
        g_fx[(rb + rg * 4 + rr) * DD + c] = fmaxf(acc[rr], 0.0f);
}

// ---------------- K5: fused output — gather xd, GEMM1, hardshrink, GEMM2, store ----
// BM = 64, threads 256: tx = t&7 (col quads 4*tx+32*j), ty = t>>3 (rows 2*ty, 2*ty+1)
// smem: O1[64][132] | XD[64][260] (reused as BS2[128][128] in stage2) | BS1[32][128] | tix[128]
#define LDO1 132
#define LDXD 260
__global__ void __launch_bounds__(256, 1)
k_out(const int* __restrict__ tpl, const float* __restrict__ oW1,
      const float* __restrict__ oB1, float* __restrict__ out, int T, int S) {
    extern __shared__ float sm[];
    float* O1  = sm;                        // 8448 floats
    float* XD  = sm + 64 * LDO1;            // 16640 floats
    float* BS1 = XD + 64 * LDXD;            // 4096 floats
    int*   tix = (int*)(BS1 + 32 * 128);    // 128 ints

    const int t  = threadIdx.x;
    const int tx = t & 7, ty = t >> 3;
    const int m0 = blockIdx.x * 64;
    const int row0 = ty * 2, row1 = ty * 2 + 1;

    if (t < 128) {
        int r = t >> 1, w = t & 1;
        int mm = m0 + r;
        tix[t] = (mm < T) ? tpl[mm * 2 + w] : 0;
    }
    __syncthreads();

    // gather xd tile [64][256] from finalX (L2-resident, 512KB)
#pragma unroll
    for (int i = 0; i < 16; i++) {
        int q = t + i * 256;
        int r = q >> 6, c4 = q & 63;
        int idx = tix[r * 2 + (c4 >= 32 ? 1 : 0)];
        float4 v = ((const float4*)(g_fx + idx * DD))[c4 & 31];
        *((float4*)(XD + r * LDXD) + c4) = v;
    }

    ull acc[2][8];
#pragma unroll
    for (int r = 0; r < 2; r++)
#pragma unroll
        for (int j = 0; j < 8; j++) acc[r][j] = 0ull;

    // ---- stage 1: out1 = xd @ outW1  (K = 256, BK = 32) ----
    for (int kc = 0; kc < 256; kc += 32) {
#pragma unroll
        for (int i = 0; i < 16; i++) {
            int lin = t + i * 256;
            int kk = lin >> 7, cc = lin & 127;
            BS1[kk * 128 + cc] = oW1[(kc + kk) * DD + cc];
        }
        __syncthreads();
#pragma unroll 4
        for (int kk = 0; kk < 32; kk++) {
            ull a0 = dup2(XD[row0 * LDXD + kc + kk]);
            ull a1 = dup2(XD[row1 * LDXD + kc + kk]);
            const float* bp = BS1 + kk * 128 + tx * 4;
#pragma unroll
            for (int j = 0; j < 4; j++) {
                ulonglong2 bv = *(const ulonglong2*)(bp + j * 32);
                fma2(acc[0][j * 2],     a0, bv.x);
                fma2(acc[0][j * 2 + 1], a0, bv.y);
                fma2(acc[1][j * 2],     a1, bv.x);
                fma2(acc[1][j * 2 + 1], a1, bv.y);
            }
        }
        __syncthreads();
    }
    // epilogue 1: bias + hardshrink -> O1
#pragma unroll
    for (int r = 0; r < 2; r++) {
        int row = ty * 2 + r;
#pragma unroll
        for (int j = 0; j < 4; j++) {
            int col = tx * 4 + j * 32;
            float2 p0 = unpack2(acc[r][j * 2]);
            float2 p1 = unpack2(acc[r][j * 2 + 1]);
            float4 o;
            o.x = hshrink(p0.x + oB1[col]);
            o.y = hshrink(p0.y + oB1[col + 1]);
            o.z = hshrink(p1.x + oB1[col + 2]);
            o.w = hshrink(p1.y + oB1[col + 3]);
            *(float4*)(O1 + row * LDO1 + col) = o;
        }
    }
    __syncthreads();

    // ---- stage 2: out = hardshrink(O1 @ W2sel + b2sel), N chunks of 128 ----
    float* BS2 = XD;  // XD region reused (16384 <= 16640 floats)
    for (int n0 = 0; n0 < S; n0 += 128) {
#pragma unroll 8
        for (int i = 0; i < 64; i++) {
            int lin = t + i * 256;
            int kk = lin >> 7, cc = lin & 127;
            int col = n0 + cc;
            BS2[kk * 128 + cc] = (col < S) ? g_w2s[kk * S + col] : 0.0f;
        }
        __syncthreads();
#pragma unroll
        for (int r = 0; r < 2; r++)
#pragma unroll
            for (int j = 0; j < 8; j++) acc[r][j] = 0ull;
#pragma unroll 4
        for (int kk = 0; kk < 128; kk++) {
            ull a0 = dup2(O1[row0 * LDO1 + kk]);
            ull a1 = dup2(O1[row1 * LDO1 + kk]);
            const float* bp = BS2 + kk * 128 + tx * 4;
#pragma unroll
            for (int j = 0; j < 4; j++) {
                ulonglong2 bv = *(const ulonglong2*)(bp + j * 32);
                fma2(acc[0][j * 2],     a0, bv.x);
                fma2(acc[0][j * 2 + 1], a0, bv.y);
                fma2(acc[1][j * 2],     a1, bv.x);
                fma2(acc[1][j * 2 + 1], a1, bv.y);
            }
        }
        // epilogue 2: bias + hardshrink -> gmem (coalesced float4)
#pragma unroll
        for (int r = 0; r < 2; r++) {
            int m = m0 + ty * 2 + r;
            if (m < T) {
#pragma unroll
                for (int j = 0; j < 4; j++) {
                    int col = n0 + tx * 4 + j * 32;
                    if (col < S) {   // S % 4 == 0, quad fully valid
                        float2 p0 = unpack2(acc[r][j * 2]);
                        float2 p1 = unpack2(acc[r][j * 2 + 1]);
                        float4 o;
                        o.x = hshrink(p0.x + g_b2s[col]);
                        o.y = hshrink(p0.y + g_b2s[col + 1]);
                        o.z = hshrink(p1.x + g_b2s[col + 2]);
                        o.w = hshrink(p1.y + g_b2s[col + 3]);
                        *(float4*)(out + (size_t)m * S + col) = o;
                    }
                }
            }
        }
        __syncthreads();
    }
}

// ---------------- host ----------------
extern "C" void kernel_launch(void* const* d_in, const int* in_sizes, int n_in,
                              void* d_out, int out_size) {
    const float* drugF = (const float*)d_in[0];
    const int*   ei    = (const int*)d_in[1];
    const int*   tpl   = (const int*)d_in[2];
    const int*   ses   = (const int*)d_in[3];
    const float* W1    = (const float*)d_in[4];
    const float* b1    = (const float*)d_in[5];
    const float* W2    = (const float*)d_in[6];
    const float* b2    = (const float*)d_in[7];
    const float* pe    = (const float*)d_in[8];
    const float* Wl    = (const float*)d_in[9];
    const float* bl    = (const float*)d_in[10];
    const float* Wr    = (const float*)d_in[11];
    const float* oW1   = (const float*)d_in[12];
    const float* oB1   = (const float*)d_in[13];
    const float* oW2   = (const float*)d_in[14];
    const float* oB2   = (const float*)d_in[15];

    const int E   = in_sizes[1] / 2;
    const int T   = in_sizes[2] / 2;
    const int S   = in_sizes[3];
    const int nSe = in_sizes[15];
    float* out = (float*)d_out;

    const int smem5 = (64 * LDO1 + 64 * LDXD + 32 * 128) * 4 + 128 * 4;  // 117248
    cudaFuncSetAttribute(k_out, cudaFuncAttributeMaxDynamicSharedMemorySize, smem5);

    k_zero<<<(ND * DD + 255) / 256, 256>>>();
    k_mlp1<<<dim3((ND + 15) / 16, SK), 256>>>(drugF, W1);
    k_mlp2<<<ND / 8, 256>>>(W2, b1, b2);
    k_agg <<<(E + 255) / 256, 256>>>(ei, pe, E);
    k_sel <<<(DD * S + 255) / 256, 256>>>(oW2, oB2, ses, S, nSe);
    k_sage<<<ND / 8, 256>>>(Wl, bl, Wr);
    k_out <<<(T + 63) / 64, 256, smem5>>>(tpl, oW1, oB1, out, T, S);
}

// round 3
// speedup vs baseline: 4.8272x; 4.8272x over previous
#include <cuda_runtime.h>
#include <cuda_bf16.h>
#include <cstdint>
#include <cmath>

#define ND    1000
#define FIN   2048
#define DD    128
#define LAMBD 1e-6f
#define SK    4

// ---------------- device scratch ----------------
__device__ __align__(16) float g_h1[ND * DD];
__device__ __align__(16) float g_h [ND * DD];
__device__ __align__(16) float g_agg[ND * DD];
__device__ float g_cnt[ND];
__device__ __align__(16) __nv_bfloat16 g_fxhi[ND * DD];
__device__ __align__(16) __nv_bfloat16 g_fxlo[ND * DD];
__device__ __align__(16) __nv_bfloat16 g_w1thi[DD * 256];   // [n=128][k=256] = outW1^T
__device__ __align__(16) __nv_bfloat16 g_w1tlo[DD * 256];
__device__ __align__(16) __nv_bfloat16 g_w2thi[512 * DD];   // [n=512][k=128] = selected outW2^T
__device__ __align__(16) __nv_bfloat16 g_w2tlo[512 * DD];
__device__ __align__(16) float g_b2s[512];

// ---------------- helpers ----------------
__device__ __forceinline__ float hshrink(float v) { return (fabsf(v) > LAMBD) ? v : 0.0f; }

__device__ __forceinline__ uint32_t smem_u32(const void* p) {
    uint32_t a;
    asm("{ .reg .u64 t; cvta.to.shared.u64 t, %1; cvt.u32.u64 %0, t; }" : "=r"(a) : "l"(p));
    return a;
}
__device__ __forceinline__ void ldmx4(uint32_t* r, uint32_t a) {
    asm volatile("ldmatrix.sync.aligned.m8n8.x4.shared.b16 {%0,%1,%2,%3}, [%4];"
                 : "=r"(r[0]), "=r"(r[1]), "=r"(r[2]), "=r"(r[3]) : "r"(a));
}
__device__ __forceinline__ void ldmx2(uint32_t* r, uint32_t a) {
    asm volatile("ldmatrix.sync.aligned.m8n8.x2.shared.b16 {%0,%1}, [%2];"
                 : "=r"(r[0]), "=r"(r[1]) : "r"(a));
}
__device__ __forceinline__ void mma16816(float* c, const uint32_t* a, const uint32_t* b) {
    asm volatile(
        "mma.sync.aligned.m16n8k16.row.col.f32.bf16.bf16.f32 "
        "{%0,%1,%2,%3}, {%4,%5,%6,%7}, {%8,%9}, {%0,%1,%2,%3};"
        : "+f"(c[0]), "+f"(c[1]), "+f"(c[2]), "+f"(c[3])
        : "r"(a[0]), "r"(a[1]), "r"(a[2]), "r"(a[3]), "r"(b[0]), "r"(b[1]));
}
__device__ __forceinline__ uint32_t packbf2(float a, float b) {
    __nv_bfloat162 h = __floats2bfloat162_rn(a, b);
    return *(uint32_t*)&h;
}

// ---------------- K0: zero scratch ----------------
__global__ void k_zero() {
    int i = blockIdx.x * 256 + threadIdx.x;
    if (i < ND * DD) { g_h1[i] = 0.0f; g_agg[i] = 0.0f; }
    if (i < ND) g_cnt[i] = 0.0f;
}

// ---------------- K1: h1 = drugF @ W1 (split-K, atomic) ----------------
__global__ void k_mlp1(const float* __restrict__ dF, const float* __restrict__ W1) {
    __shared__ float As[16][33];
    __shared__ float Bs[32][128];
    const int rb = blockIdx.x * 16;
    const int k0 = blockIdx.y * (FIN / SK);
    const int t  = threadIdx.x;
    const int c  = t & 127, rg = t >> 7;
    float acc[8];
#pragma unroll
    for (int r = 0; r < 8; r++) acc[r] = 0.0f;
    for (int kb = 0; kb < FIN / SK; kb += 32) {
        {
            int kk = t & 31, r = t >> 5;
#pragma unroll
            for (int i = 0; i < 2; i++) {
                int rr = r + i * 8, grow = rb + rr;
                As[rr][kk] = (grow < ND) ? dF[(size_t)grow * FIN + k0 + kb + kk] : 0.0f;
            }
        }
#pragma unroll
        for (int i = 0; i < 16; i++) {
            int lin = t + i * 256, kk = lin >> 7, cc = lin & 127;
            Bs[kk][cc] = W1[(size_t)(k0 + kb + kk) * DD + cc];
        }
        __syncthreads();
#pragma unroll 8
        for (int kk = 0; kk < 32; kk++) {
            float b = Bs[kk][c];
#pragma unroll
            for (int rr = 0; rr < 8; rr++) acc[rr] += As[rg * 8 + rr][kk] * b;
        }
        __syncthreads();
    }
#pragma unroll
    for (int rr = 0; rr < 8; rr++) {
        int grow = rb + rg * 8 + rr;
        if (grow < ND) atomicAdd(&g_h1[grow * DD + c], acc[rr]);
    }
}

// ---------------- K2: h = relu(relu(h1+b1) @ W2 + b2) ----------------
__global__ void k_mlp2(const float* __restrict__ W2, const float* __restrict__ b1,
                       const float* __restrict__ b2) {
    __shared__ float hs[8][128];
    const int rb = blockIdx.x * 8;
    const int t  = threadIdx.x;
#pragma unroll
    for (int i = 0; i < 4; i++) {
        int lin = t + i * 256, r = lin >> 7, cc = lin & 127;
        hs[r][cc] = fmaxf(g_h1[(rb + r) * DD + cc] + b1[cc], 0.0f);
    }
    __syncthreads();
    const int c = t & 127, rg = t >> 7;
    float acc[4];
#pragma unroll
    for (int rr = 0; rr < 4; rr++) acc[rr] = b2[c];
#pragma unroll 4
    for (int k = 0; k < 128; k++) {
        float w = W2[k * DD + c];
#pragma unroll
        for (int rr = 0; rr < 4; rr++) acc[rr] += hs[rg * 4 + rr][k] * w;
    }
#pragma unroll
    for (int rr = 0; rr < 4; rr++)
        g_h[(rb + rg * 4 + rr) * DD + c] = fmaxf(acc[rr], 0.0f);
}

// ---------------- K3: edge aggregation (only dst < ND matters) ----------------
__global__ void k_agg(const int* __restrict__ ei, const float* __restrict__ pe, int E) {
    const int e = blockIdx.x * 256 + threadIdx.x;
    const int lane = threadIdx.x & 31;
    int dst = 0, src = 0;
    bool act = false;
    if (e < E) {
        dst = ei[E + e];
        act = (dst < ND);
        if (act) src = ei[e];
    }
    unsigned m = __ballot_sync(0xffffffffu, act);
    while (m) {
        int leader = __ffs(m) - 1;
        m &= m - 1;
        int d = __shfl_sync(0xffffffffu, dst, leader);
        int s = __shfl_sync(0xffffffffu, src, leader);
        const float4* p = (s < ND) ? (const float4*)(g_h + s * DD)
                                   : (const float4*)(pe + (size_t)(s - ND) * DD);
        float4 v = p[lane];
        float* ap = g_agg + d * DD + lane * 4;
        asm volatile("red.global.add.v4.f32 [%0], {%1,%2,%3,%4};"
                     :: "l"(ap), "f"(v.x), "f"(v.y), "f"(v.z), "f"(v.w) : "memory");
        if (lane == 0) atomicAdd(&g_cnt[d], 1.0f);
    }
}

// ---------------- K4: weight prep — transpose + bf16 hi/lo split ----------------
__global__ void k_prepw(const float* __restrict__ oW1, const float* __restrict__ oW2,
                        const float* __restrict__ oB2, const int* __restrict__ ses,
                        int S, int nSe) {
    int i = blockIdx.x * 256 + threadIdx.x;
    if (i < DD * 256) {                       // w1t[n][k] = oW1[k][n]
        int n = i >> 8, k = i & 255;
        float v = oW1[(size_t)k * DD + n];
        __nv_bfloat16 h = __float2bfloat16(v);
        g_w1thi[i] = h;
        g_w1tlo[i] = __float2bfloat16(v - __bfloat162float(h));
    } else if (i < DD * 256 + 512 * DD) {     // w2t[n][k] = oW2[k][ses[n]]
        int j = i - DD * 256;
        int n = j >> 7, k = j & 127;
        float v = (n < S) ? oW2[(size_t)k * nSe + ses[n]] : 0.0f;
        __nv_bfloat16 h = __float2bfloat16(v);
        g_w2thi[j] = h;
        g_w2tlo[j] = __float2bfloat16(v - __bfloat162float(h));
    } else if (i < DD * 256 + 512 * DD + 512) {
        int n = i - DD * 256 - 512 * DD;
        g_b2s[n] = (n < S) ? oB2[ses[n]] : 0.0f;
    }
}

// ---------------- K5: finalX = relu(mean @ Wl + bl + h @ Wr), bf16 hi/lo ------
__global__ void k_sage(const float* __restrict__ Wl, const float* __restrict__ bl,
                       const float* __restrict__ Wr) {
    __shared__ float ms[8][128];
    __shared__ float hs[8][128];
    const int rb = blockIdx.x * 8;
    const int t  = threadIdx.x;
#pragma unroll
    for (int i = 0; i < 4; i++) {
        int lin = t + i * 256, r = lin >> 7, cc = lin & 127;
        float cnt = fmaxf(g_cnt[rb + r], 1.0f);
        ms[r][cc] = g_agg[(rb + r) * DD + cc] / cnt;
        hs[r][cc] = g_h[(rb + r) * DD + cc];
    }
    __syncthreads();
    const int c = t & 127, rg = t >> 7;
    float acc[4];
#pragma unroll
    for (int rr = 0; rr < 4; rr++) acc[rr] = bl[c];
#pragma unroll 4
    for (int k = 0; k < 128; k++) {
        float wl = Wl[k * DD + c];
        float wr = Wr[k * DD + c];
#pragma unroll
        for (int rr = 0; rr < 4; rr++)
            acc[rr] += ms[rg * 4 + rr][k] * wl + hs[rg * 4 + rr][k] * wr;
    }
#pragma unroll
    for (int rr = 0; rr < 4; rr++) {
        float v = fmaxf(acc[rr], 0.0f);
        int o = (rb + rg * 4 + rr) * DD + c;
        __nv_bfloat16 h = __float2bfloat16(v);
        g_fxhi[o] = h;
        g_fxlo[o] = __float2bfloat16(v - __bfloat162float(h));
    }
}

// ---------------- K6: fused output via warp MMA (bf16 hi/lo x3) --------------
// CTA tile 128x128, 8 warps 2(M)x4(N), warp tile 64x32, acc[4][4][4].
// smem: Ah[128][136]bf16 | Al | Bh[128][136] | Bl | tix[256]
#define LDA    136
#define SM_AH  0
#define SM_AL  34816
#define SM_BH  69632
#define SM_BL  104448
#define SM_TIX 139264
#define SM_TOT 140288

__device__ __forceinline__ void compute_chunk(uint32_t sb, float acc[4][4][4],
                                              int wm, int wn, int lane) {
    const int p  = lane & 15;
    const int bn = p & 7;
    const int ar = lane & 15;
#pragma unroll
    for (int kk = 0; kk < 8; kk++) {
        uint32_t bh[4][2], bl[4][2];
        const int bk = kk * 16 + (p >> 3) * 8;
#pragma unroll
        for (int j = 0; j < 4; j++) {
            uint32_t ba = sb + SM_BH + (uint32_t)((wn * 32 + j * 8 + bn) * LDA + bk) * 2;
            ldmx2(bh[j], ba);
            ldmx2(bl[j], ba + (SM_BL - SM_BH));
        }
        const int ac = kk * 16 + (lane >> 4) * 8;
#pragma unroll
        for (int i = 0; i < 4; i++) {
            uint32_t a[4];
            uint32_t aa = sb + SM_AH + (uint32_t)((wm * 64 + i * 16 + ar) * LDA + ac) * 2;
            ldmx4(a, aa);
#pragma unroll
            for (int j = 0; j < 4; j++) {
                mma16816(acc[i][j], a, bh[j]);   // hi * hi (or hi*hi path)
                mma16816(acc[i][j], a, bl[j]);   // hi * lo
            }
            ldmx4(a, aa + (SM_AL - SM_AH));
#pragma unroll
            for (int j = 0; j < 4; j++)
                mma16816(acc[i][j], a, bh[j]);   // lo * hi
        }
    }
}

__global__ void __launch_bounds__(256, 1)
k_out(const int* __restrict__ tpl, const float* __restrict__ oB1,
      float* __restrict__ out, int T, int S) {
    extern __shared__ char smem[];
    const uint32_t sb = smem_u32(smem);
    const int t = threadIdx.x, lane = t & 31, wid = t >> 5;
    const int wm = wid & 1, wn = wid >> 1;
    const int m0 = blockIdx.x * 128;
    int* tix = (int*)(smem + SM_TIX);
    {
        int r = t >> 1, w = t & 1, mm = m0 + r;
        tix[t] = (mm < T) ? tpl[mm * 2 + w] : 0;
    }

    float acc[4][4][4];
#pragma unroll
    for (int i = 0; i < 4; i++)
#pragma unroll
        for (int j = 0; j < 4; j++)
#pragma unroll
            for (int c = 0; c < 4; c++) acc[i][j][c] = 0.0f;

    // ---- stage 1: O1 = hardshrink(xd @ outW1 + b1), K = 256 in 2 chunks ----
    for (int kc = 0; kc < 2; kc++) {
        __syncthreads();
#pragma unroll
        for (int it = 0; it < 8; it++) {
            int q = t + it * 256, r = q >> 4, c = q & 15;
            int idx = tix[r * 2 + kc];
            float4 vh = ((const float4*)(g_fxhi + (size_t)idx * DD))[c];
            float4 vl = ((const float4*)(g_fxlo + (size_t)idx * DD))[c];
            uint32_t off = (uint32_t)(r * LDA + c * 8) * 2;
            *(float4*)(smem + SM_AH + off) = vh;
            *(float4*)(smem + SM_AL + off) = vl;
            float4 wh = ((const float4*)(g_w1thi + r * 256 + kc * 128))[c];
            float4 wl = ((const float4*)(g_w1tlo + r * 256 + kc * 128))[c];
            *(float4*)(smem + SM_BH + off) = wh;
            *(float4*)(smem + SM_BL + off) = wl;
        }
        __syncthreads();
        compute_chunk(sb, acc, wm, wn, lane);
    }
    __syncthreads();

    // ---- epilogue 1: bias + hardshrink, bf16 hi/lo split -> A buffers ----
    const int g = lane >> 2, cq = (lane & 3) * 2;
#pragma unroll
    for (int i = 0; i < 4; i++) {
#pragma unroll
        for (int j = 0; j < 4; j++) {
            int c0 = wn * 32 + j * 8 + cq;
            int r0 = wm * 64 + i * 16 + g;
            float bA = oB1[c0], bB = oB1[c0 + 1];
            float v00 = hshrink(acc[i][j][0] + bA);
            float v01 = hshrink(acc[i][j][1] + bB);
            float v10 = hshrink(acc[i][j][2] + bA);
            float v11 = hshrink(acc[i][j][3] + bB);
            __nv_bfloat16 h00 = __float2bfloat16(v00), h01 = __float2bfloat16(v01);
            __nv_bfloat16 h10 = __float2bfloat16(v10), h11 = __float2bfloat16(v11);
            float l00 = v00 - __bfloat162float(h00), l01 = v01 - __bfloat162float(h01);
            float l10 = v10 - __bfloat162float(h10), l11 = v11 - __bfloat162float(h11);
            uint32_t o0 = (uint32_t)(r0 * LDA + c0) * 2;
            uint32_t o1 = (uint32_t)((r0 + 8) * LDA + c0) * 2;
            *(uint32_t*)(smem + SM_AH + o0) =
                (uint32_t)__bfloat16_as_ushort(h00) | ((uint32_t)__bfloat16_as_ushort(h01) << 16);
            *(uint32_t*)(smem + SM_AH + o1) =
                (uint32_t)__bfloat16_as_ushort(h10) | ((uint32_t)__bfloat16_as_ushort(h11) << 16);
            *(uint32_t*)(smem + SM_AL + o0) = packbf2(l00, l01);
            *(uint32_t*)(smem + SM_AL + o1) = packbf2(l10, l11);
        }
    }
    __syncthreads();

    // ---- stage 2: out = hardshrink(O1 @ W2sel + b2sel), N = 512 in 4 chunks ----
    for (int nc = 0; nc < 4; nc++) {
#pragma unroll
        for (int it = 0; it < 8; it++) {
            int q = t + it * 256, n = q >> 4, c = q & 15;
            float4 wh = ((const float4*)(g_w2thi + (size_t)(nc * 128 + n) * DD))[c];
            float4 wl = ((const float4*)(g_w2tlo + (size_t)(nc * 128 + n) * DD))[c];
            uint32_t off = (uint32_t)(n * LDA + c * 8) * 2;
            *(float4*)(smem + SM_BH + off) = wh;
            *(float4*)(smem + SM_BL + off) = wl;
        }
        __syncthreads();
#pragma unroll
        for (int i = 0; i < 4; i++)
#pragma unroll
            for (int j = 0; j < 4; j++)
#pragma unroll
                for (int c = 0; c < 4; c++) acc[i][j][c] = 0.0f;
        compute_chunk(sb, acc, wm, wn, lane);
        // epilogue: direct coalesced-sector global stores
#pragma unroll
        for (int i = 0; i < 4; i++) {
#pragma unroll
            for (int j = 0; j < 4; j++) {
                int gc = nc * 128 + wn * 32 + j * 8 + cq;
                if (gc < S) {
                    float bA = g_b2s[gc], bB = g_b2s[gc + 1];
                    int r0 = wm * 64 + i * 16 + g;
                    int mA = m0 + r0, mB = mA + 8;
                    if (mA < T) {
                        float2 o = { hshrink(acc[i][j][0] + bA), hshrink(acc[i][j][1] + bB) };
                        *(float2*)(out + (size_t)mA * S + gc) = o;
                    }
                    if (mB < T) {
                        float2 o = { hshrink(acc[i][j][2] + bA), hshrink(acc[i][j][3] + bB) };
                        *(float2*)(out + (size_t)mB * S + gc) = o;
                    }
                }
            }
        }
        __syncthreads();
    }
}

// ---------------- host ----------------
extern "C" void kernel_launch(void* const* d_in, const int* in_sizes, int n_in,
                              void* d_out, int out_size) {
    const float* drugF = (const float*)d_in[0];
    const int*   ei    = (const int*)d_in[1];
    const int*   tpl   = (const int*)d_in[2];
    const int*   ses   = (const int*)d_in[3];
    const float* W1    = (const float*)d_in[4];
    const float* b1    = (const float*)d_in[5];
    const float* W2    = (const float*)d_in[6];
    const float* b2    = (const float*)d_in[7];
    const float* pe    = (const float*)d_in[8];
    const float* Wl    = (const float*)d_in[9];
    const float* bl    = (const float*)d_in[10];
    const float* Wr    = (const float*)d_in[11];
    const float* oW1   = (const float*)d_in[12];
    const float* oB1   = (const float*)d_in[13];
    const float* oW2   = (const float*)d_in[14];
    const float* oB2   = (const float*)d_in[15];

    const int E   = in_sizes[1] / 2;
    const int T   = in_sizes[2] / 2;
    const int S   = in_sizes[3];
    const int nSe = in_sizes[15];
    float* out = (float*)d_out;

    cudaFuncSetAttribute(k_out, cudaFuncAttributeMaxDynamicSharedMemorySize, SM_TOT);

    const int prepN = DD * 256 + 512 * DD + 512;

    k_zero <<<(ND * DD + 255) / 256, 256>>>();
    k_mlp1 <<<dim3((ND + 15) / 16, SK), 256>>>(drugF, W1);
    k_mlp2 <<<ND / 8, 256>>>(W2, b1, b2);
    k_agg  <<<(E + 255) / 256, 256>>>(ei, pe, E);
    k_prepw<<<(prepN + 255) / 256, 256>>>(oW1, oW2, oB2, ses, S, nSe);
    k_sage <<<ND / 8, 256>>>(Wl, bl, Wr);
    k_out  <<<(T + 127) / 128, 256, SM_TOT>>>(tpl, oB1, out, T, S);
}

// round 4
// speedup vs baseline: 5.7788x; 1.1971x over previous
#include <cuda_runtime.h>
#include <cuda_bf16.h>
#include <cuda_fp16.h>
#include <cstdint>
#include <cmath>

#define ND    1000
#define FIN   2048
#define DD    128
#define LAMBD 1e-6f
#define SK    8

// ---------------- device scratch ----------------
__device__ __align__(16) float g_h1[ND * DD];
__device__ __align__(16) float g_h [ND * DD];
__device__ __align__(16) float g_agg[ND * DD];
__device__ float g_cnt[ND];
__device__ __align__(16) __half g_fxh [ND * DD];      // finalX fp16
__device__ __align__(16) __half g_w1th[DD * 256];     // outW1^T hi  [n=128][k=256]
__device__ __align__(16) __half g_w1tl[DD * 256];     // outW1^T lo
__device__ __align__(16) __half g_w2th[512 * DD];     // selected outW2^T hi [n=512][k=128]
__device__ __align__(16) __half g_w2tl[512 * DD];
__device__ __align__(16) float g_b2s[512];

// ---------------- helpers ----------------
__device__ __forceinline__ float hshrink(float v) { return (fabsf(v) > LAMBD) ? v : 0.0f; }

__device__ __forceinline__ uint32_t smem_u32(const void* p) {
    uint32_t a;
    asm("{ .reg .u64 t; cvta.to.shared.u64 t, %1; cvt.u32.u64 %0, t; }" : "=r"(a) : "l"(p));
    return a;
}
__device__ __forceinline__ void ldmx4(uint32_t* r, uint32_t a) {
    asm volatile("ldmatrix.sync.aligned.m8n8.x4.shared.b16 {%0,%1,%2,%3}, [%4];"
                 : "=r"(r[0]), "=r"(r[1]), "=r"(r[2]), "=r"(r[3]) : "r"(a));
}
__device__ __forceinline__ void mma16816h(float* c, const uint32_t* a, const uint32_t* b) {
    asm volatile(
        "mma.sync.aligned.m16n8k16.row.col.f32.f16.f16.f32 "
        "{%0,%1,%2,%3}, {%4,%5,%6,%7}, {%8,%9}, {%0,%1,%2,%3};"
        : "+f"(c[0]), "+f"(c[1]), "+f"(c[2]), "+f"(c[3])
        : "r"(a[0]), "r"(a[1]), "r"(a[2]), "r"(a[3]), "r"(b[0]), "r"(b[1]));
}
__device__ __forceinline__ void cpa16(uint32_t d, const void* s) {
    asm volatile("cp.async.cg.shared.global [%0], [%1], 16;"
                 :: "r"(d), "l"(__cvta_generic_to_global(s)) : "memory");
}
#define CP_COMMIT() asm volatile("cp.async.commit_group;" ::: "memory")

// ---------------- K0: zero scratch ----------------
__global__ void k_zero() {
    int i = blockIdx.x * 256 + threadIdx.x;
    if (i < ND * DD) { g_h1[i] = 0.0f; g_agg[i] = 0.0f; }
    if (i < ND) g_cnt[i] = 0.0f;
}

// ---------------- K1: h1 = drugF @ W1 (split-K, atomic) ----------------
__global__ void k_mlp1(const float* __restrict__ dF, const float* __restrict__ W1) {
    __shared__ float As[16][33];
    __shared__ float Bs[32][128];
    const int rb = blockIdx.x * 16;
    const int k0 = blockIdx.y * (FIN / SK);
    const int t  = threadIdx.x;
    const int c  = t & 127, rg = t >> 7;
    float acc[8];
#pragma unroll
    for (int r = 0; r < 8; r++) acc[r] = 0.0f;
    for (int kb = 0; kb < FIN / SK; kb += 32) {
        {
            int kk = t & 31, r = t >> 5;
#pragma unroll
            for (int i = 0; i < 2; i++) {
                int rr = r + i * 8, grow = rb + rr;
                As[rr][kk] = (grow < ND) ? dF[(size_t)grow * FIN + k0 + kb + kk] : 0.0f;
            }
        }
#pragma unroll
        for (int i = 0; i < 16; i++) {
            int lin = t + i * 256, kk = lin >> 7, cc = lin & 127;
            Bs[kk][cc] = W1[(size_t)(k0 + kb + kk) * DD + cc];
        }
        __syncthreads();
#pragma unroll 8
        for (int kk = 0; kk < 32; kk++) {
            float b = Bs[kk][c];
#pragma unroll
            for (int rr = 0; rr < 8; rr++) acc[rr] += As[rg * 8 + rr][kk] * b;
        }
        __syncthreads();
    }
#pragma unroll
    for (int rr = 0; rr < 8; rr++) {
        int grow = rb + rg * 8 + rr;
        if (grow < ND) atomicAdd(&g_h1[grow * DD + c], acc[rr]);
    }
}

// ---------------- K2: h = relu(relu(h1+b1) @ W2 + b2) ----------------
__global__ void k_mlp2(const float* __restrict__ W2, const float* __restrict__ b1,
                       const float* __restrict__ b2) {
    __shared__ float hs[8][128];
    const int rb = blockIdx.x * 8;
    const int t  = threadIdx.x;
#pragma unroll
    for (int i = 0; i < 4; i++) {
        int lin = t + i * 256, r = lin >> 7, cc = lin & 127;
        hs[r][cc] = fmaxf(g_h1[(rb + r) * DD + cc] + b1[cc], 0.0f);
    }
    __syncthreads();
    const int c = t & 127, rg = t >> 7;
    float acc[4];
#pragma unroll
    for (int rr = 0; rr < 4; rr++) acc[rr] = b2[c];
#pragma unroll 4
    for (int k = 0; k < 128; k++) {
        float w = W2[k * DD + c];
#pragma unroll
        for (int rr = 0; rr < 4; rr++) acc[rr] += hs[rg * 4 + rr][k] * w;
    }
#pragma unroll
    for (int rr = 0; rr < 4; rr++)
        g_h[(rb + rg * 4 + rr) * DD + c] = fmaxf(acc[rr], 0.0f);
}

// ---------------- K3: edge aggregation (only dst < ND matters) ----------------
__global__ void k_agg(const int* __restrict__ ei, const float* __restrict__ pe, int E) {
    const int e = blockIdx.x * 256 + threadIdx.x;
    const int lane = threadIdx.x & 31;
    int dst = 0, src = 0;
    bool act = false;
    if (e < E) {
        dst = ei[E + e];
        act = (dst < ND);
        if (act) src = ei[e];
    }
    unsigned m = __ballot_sync(0xffffffffu, act);
    while (m) {
        int leader = __ffs(m) - 1;
        m &= m - 1;
        int d = __shfl_sync(0xffffffffu, dst, leader);
        int s = __shfl_sync(0xffffffffu, src, leader);
        const float4* p = (s < ND) ? (const float4*)(g_h + s * DD)
                                   : (const float4*)(pe + (size_t)(s - ND) * DD);
        float4 v = p[lane];
        float* ap = g_agg + d * DD + lane * 4;
        asm volatile("red.global.add.v4.f32 [%0], {%1,%2,%3,%4};"
                     :: "l"(ap), "f"(v.x), "f"(v.y), "f"(v.z), "f"(v.w) : "memory");
        if (lane == 0) atomicAdd(&g_cnt[d], 1.0f);
    }
}

// ---------------- K4: weight prep — transpose + fp16 hi/lo split ----------------
__global__ void k_prepw(const float* __restrict__ oW1, const float* __restrict__ oW2,
                        const float* __restrict__ oB2, const int* __restrict__ ses,
                        int S, int nSe) {
    int i = blockIdx.x * 256 + threadIdx.x;
    if (i < DD * 256) {                       // w1t[n][k] = oW1[k][n]
        int n = i >> 8, k = i & 255;
        float v = oW1[(size_t)k * DD + n];
        __half h = __float2half_rn(v);
        g_w1th[i] = h;
        g_w1tl[i] = __float2half_rn(v - __half2float(h));
    } else if (i < DD * 256 + 512 * DD) {     // w2t[n][k] = oW2[k][ses[n]]
        int j = i - DD * 256;
        int n = j >> 7, k = j & 127;
        float v = (n < S) ? oW2[(size_t)k * nSe + ses[n]] : 0.0f;
        __half h = __float2half_rn(v);
        g_w2th[j] = h;
        g_w2tl[j] = __float2half_rn(v - __half2float(h));
    } else if (i < DD * 256 + 512 * DD + 512) {
        int n = i - DD * 256 - 512 * DD;
        g_b2s[n] = (n < S) ? oB2[ses[n]] : 0.0f;
    }
}

// ---------------- K5: finalX = relu(mean @ Wl + bl + h @ Wr), fp16 out --------
__global__ void k_sage(const float* __restrict__ Wl, const float* __restrict__ bl,
                       const float* __restrict__ Wr) {
    __shared__ float ms[8][128];
    __shared__ float hs[8][128];
    const int rb = blockIdx.x * 8;
    const int t  = threadIdx.x;
#pragma unroll
    for (int i = 0; i < 4; i++) {
        int lin = t + i * 256, r = lin >> 7, cc = lin & 127;
        float cnt = fmaxf(g_cnt[rb + r], 1.0f);
        ms[r][cc] = g_agg[(rb + r) * DD + cc] / cnt;
        hs[r][cc] = g_h[(rb + r) * DD + cc];
    }
    __syncthreads();
    const int c = t & 127, rg = t >> 7;
    float acc[4];
#pragma unroll
    for (int rr = 0; rr < 4; rr++) acc[rr] = bl[c];
#pragma unroll 4
    for (int k = 0; k < 128; k++) {
        float wl = Wl[k * DD + c];
        float wr = Wr[k * DD + c];
#pragma unroll
        for (int rr = 0; rr < 4; rr++)
            acc[rr] += ms[rg * 4 + rr][k] * wl + hs[rg * 4 + rr][k] * wr;
    }
#pragma unroll
    for (int rr = 0; rr < 4; rr++) {
        float v = fmaxf(acc[rr], 0.0f);
        g_fxh[(rb + rg * 4 + rr) * DD + c] = __float2half_rn(v);
    }
}

// ---------------- K6: fused output — fp16 MMA, B hi/lo, cp.async pipeline ----
// CTA tile 128x128, 8 warps 2(M)x4(N), warp tile 64x32, acc[4][4][4].
// 6 phases: p=0,1 stage-1 K-chunks; p=2..5 stage-2 N-chunks. 2-deep cp.async pipe.
#define LDA     136
#define ABYTES  34816                 // 128*136*2
#define BBYTES  69632                 // (hi+lo) per buffer
#define SM_A0   0
#define SM_A1   ABYTES
#define SM_B    (2*ABYTES)            // 69632: two B buffers follow
#define SM_TIX  (SM_B + 2*BBYTES)     // 208896
#define SM_TOT  (SM_TIX + 1024)       // 209920

__device__ __forceinline__ void load_phase(int p, char* smem, const int* tix, int t) {
    uint32_t sb = smem_u32(smem);
    uint32_t bh = sb + SM_B + (uint32_t)(p & 1) * BBYTES;
    uint32_t bl = bh + ABYTES;
    if (p < 2) {
#pragma unroll
        for (int it = 0; it < 8; it++) {
            int q = t + it * 256, n = q >> 4, c = q & 15;
            uint32_t off = (uint32_t)(n * LDA + c * 8) * 2;
            cpa16(bh + off, g_w1th + n * 256 + p * 128 + c * 8);
            cpa16(bl + off, g_w1tl + n * 256 + p * 128 + c * 8);
        }
        uint32_t ab = sb + (uint32_t)(p ? SM_A1 : SM_A0);
#pragma unroll
        for (int it = 0; it < 8; it++) {
            int q = t + it * 256, r = q >> 4, c = q & 15;
            int idx = tix[r * 2 + p];
            cpa16(ab + (uint32_t)(r * LDA + c * 8) * 2, g_fxh + (size_t)idx * DD + c * 8);
        }
    } else {
        int nc = p - 2;
#pragma unroll
        for (int it = 0; it < 8; it++) {
            int q = t + it * 256, n = q >> 4, c = q & 15;
            uint32_t off = (uint32_t)(n * LDA + c * 8) * 2;
            cpa16(bh + off, g_w2th + (size_t)(nc * 128 + n) * DD + c * 8);
            cpa16(bl + off, g_w2tl + (size_t)(nc * 128 + n) * DD + c * 8);
        }
    }
}

__device__ __forceinline__ void compute_f16(uint32_t aBase, uint32_t bhBase,
                                            float acc[4][4][4],
                                            int wm, int wn, int lane) {
    const int ar   = lane & 15;
    const int ac8  = (lane >> 4) * 8;
    const int brow = ((lane >> 4) & 1) * 8 + (lane & 7);
    const int bcol = ((lane >> 3) & 1) * 8;
#pragma unroll
    for (int kk = 0; kk < 8; kk++) {
        uint32_t bhf[2][4], blf[2][4];
#pragma unroll
        for (int j2 = 0; j2 < 2; j2++) {
            uint32_t ba = bhBase +
                (uint32_t)((wn * 32 + j2 * 16 + brow) * LDA + kk * 16 + bcol) * 2;
            ldmx4(bhf[j2], ba);
            ldmx4(blf[j2], ba + ABYTES);
        }
#pragma unroll
        for (int i = 0; i < 4; i++) {
            uint32_t a[4];
            ldmx4(a, aBase + (uint32_t)((wm * 64 + i * 16 + ar) * LDA + kk * 16 + ac8) * 2);
#pragma unroll
            for (int j2 = 0; j2 < 2; j2++) {
#pragma unroll
                for (int jj = 0; jj < 2; jj++) {
                    mma16816h(acc[i][j2 * 2 + jj], a, &bhf[j2][jj * 2]);
                    mma16816h(acc[i][j2 * 2 + jj], a, &blf[j2][jj * 2]);
                }
            }
        }
    }
}

__global__ void __launch_bounds__(256, 1)
k_out(const int* __restrict__ tpl, const float* __restrict__ oB1,
      float* __restrict__ out, int T, int S) {
    extern __shared__ char smem[];
    const uint32_t sb = smem_u32(smem);
    const int t = threadIdx.x, lane = t & 31, wid = t >> 5;
    const int wm = wid & 1, wn = wid >> 1;
    const int m0 = blockIdx.x * 128;
    int* tix = (int*)(smem + SM_TIX);
    {
        int r = t >> 1, w = t & 1, mm = m0 + r;
        tix[t] = (mm < T) ? tpl[mm * 2 + w] : 0;
    }
    __syncthreads();

    load_phase(0, smem, tix, t); CP_COMMIT();
    load_phase(1, smem, tix, t); CP_COMMIT();

    float acc[4][4][4];
#pragma unroll
    for (int i = 0; i < 4; i++)
#pragma unroll
        for (int j = 0; j < 4; j++)
#pragma unroll
            for (int c = 0; c < 4; c++) acc[i][j][c] = 0.0f;

    const int g = lane >> 2, cq = (lane & 3) * 2;

    for (int p = 0; p < 6; p++) {
        if (p < 5) asm volatile("cp.async.wait_group 1;" ::: "memory");
        else       asm volatile("cp.async.wait_group 0;" ::: "memory");
        __syncthreads();

        if (p >= 2) {
#pragma unroll
            for (int i = 0; i < 4; i++)
#pragma unroll
                for (int j = 0; j < 4; j++)
#pragma unroll
                    for (int c = 0; c < 4; c++) acc[i][j][c] = 0.0f;
        }
        uint32_t aB = sb + (uint32_t)((p < 2) ? (p ? SM_A1 : SM_A0) : SM_A0);
        uint32_t bB = sb + SM_B + (uint32_t)(p & 1) * BBYTES;
        compute_f16(aB, bB, acc, wm, wn, lane);

        if (p == 1) {
            // epilogue 1: bias + hardshrink -> fp16 O1 into A0 region
#pragma unroll
            for (int i = 0; i < 4; i++) {
#pragma unroll
                for (int j = 0; j < 4; j++) {
                    int c0 = wn * 32 + j * 8 + cq;
                    int r0 = wm * 64 + i * 16 + g;
                    float bA = oB1[c0], bB2 = oB1[c0 + 1];
                    __half2 p0 = __floats2half2_rn(hshrink(acc[i][j][0] + bA),
                                                   hshrink(acc[i][j][1] + bB2));
                    __half2 p1 = __floats2half2_rn(hshrink(acc[i][j][2] + bA),
                                                   hshrink(acc[i][j][3] + bB2));
                    *(uint32_t*)(smem + SM_A0 + (uint32_t)(r0 * LDA + c0) * 2) =
                        *(uint32_t*)&p0;
                    *(uint32_t*)(smem + SM_A0 + (uint32_t)((r0 + 8) * LDA + c0) * 2) =
                        *(uint32_t*)&p1;
                }
            }
        } else if (p >= 2) {
            int nc = p - 2;
#pragma unroll
            for (int i = 0; i < 4; i++) {
#pragma unroll
                for (int j = 0; j < 4; j++) {
                    int gc = nc * 128 + wn * 32 + j * 8 + cq;
                    if (gc < S) {
                        float bA = g_b2s[gc], bB2 = g_b2s[gc + 1];
                        int r0 = wm * 64 + i * 16 + g;
                        int mA = m0 + r0, mB = mA + 8;
                        if (mA < T) {
                            float2 o = { hshrink(acc[i][j][0] + bA),
                                         hshrink(acc[i][j][1] + bB2) };
                            *(float2*)(out + (size_t)mA * S + gc) = o;
                        }
                        if (mB < T) {
                            float2 o = { hshrink(acc[i][j][2] + bA),
                                         hshrink(acc[i][j][3] + bB2) };
                            *(float2*)(out + (size_t)mB * S + gc) = o;
                        }
                    }
                }
            }
        }
        __syncthreads();
        if (p + 2 < 6) { load_phase(p + 2, smem, tix, t); CP_COMMIT(); }
    }
}

// ---------------- host ----------------
extern "C" void kernel_launch(void* const* d_in, const int* in_sizes, int n_in,
                              void* d_out, int out_size) {
    const float* drugF = (const float*)d_in[0];
    const int*   ei    = (const int*)d_in[1];
    const int*   tpl   = (const int*)d_in[2];
    const int*   ses   = (const int*)d_in[3];
    const float* W1    = (const float*)d_in[4];
    const float* b1    = (const float*)d_in[5];
    const float* W2    = (const float*)d_in[6];
    const float* b2    = (const float*)d_in[7];
    const float* pe    = (const float*)d_in[8];
    const float* Wl    = (const float*)d_in[9];
    const float* bl    = (const float*)d_in[10];
    const float* Wr    = (const float*)d_in[11];
    const float* oW1   = (const float*)d_in[12];
    const float* oB1   = (const float*)d_in[13];
    const float* oW2   = (const float*)d_in[14];
    const float* oB2   = (const float*)d_in[15];

    const int E   = in_sizes[1] / 2;
    const int T   = in_sizes[2] / 2;
    const int S   = in_sizes[3];
    const int nSe = in_sizes[15];
    float* out = (float*)d_out;

    cudaFuncSetAttribute(k_out, cudaFuncAttributeMaxDynamicSharedMemorySize, SM_TOT);

    const int prepN = DD * 256 + 512 * DD + 512;

    k_zero <<<(ND * DD + 255) / 256, 256>>>();
    k_mlp1 <<<dim3((ND + 15) / 16, SK), 256>>>(drugF, W1);
    k_mlp2 <<<ND / 8, 256>>>(W2, b1, b2);
    k_agg  <<<(E + 255) / 256, 256>>>(ei, pe, E);
    k_prepw<<<(prepN + 255) / 256, 256>>>(oW1, oW2, oB2, ses, S, nSe);
    k_sage <<<ND / 8, 256>>>(Wl, bl, Wr);
    k_out  <<<(T + 127) / 128, 256, SM_TOT>>>(tpl, oB1, out, T, S);
}

// round 8
// speedup vs baseline: 11.6596x; 2.0176x over previous
#include <cuda_runtime.h>
#include <cstdint>
#include <cmath>

#define ND    1000
#define FIN   2048
#define DD    128
#define SK    8

// ---------------- device scratch ----------------
__device__ __align__(16) float g_h1[ND * DD];
__device__ __align__(16) float g_h [ND * DD];
__device__ __align__(16) float g_agg[ND * DD];
__device__ float g_cnt[ND];
__device__ __align__(16) float g_fx[ND * DD];       // finalX fp32
__device__ __align__(16) float g_U [256 * 512];     // U = oW1 @ oW2sel  [k=256][s=512]
__device__ __align__(16) float g_R [ND * 512];      // R = fx @ U[0:128]   (+ c folded in)
__device__ __align__(16) float g_S [ND * 512];      // S = fx @ U[128:256]
__device__ __align__(16) float g_c [512];           // c = oB1 @ oW2sel + oB2sel

// ---------------- K0: zero scratch ----------------
__global__ void k_zero() {
    int i = blockIdx.x * 256 + threadIdx.x;
    if (i < ND * DD) { g_h1[i] = 0.0f; g_agg[i] = 0.0f; }
    if (i < ND) g_cnt[i] = 0.0f;
}

// ---------------- K1: h1 = drugF @ W1 (split-K, atomic) ----------------
__global__ void k_mlp1(const float* __restrict__ dF, const float* __restrict__ W1) {
    __shared__ float As[16][33];
    __shared__ float Bs[32][128];
    const int rb = blockIdx.x * 16;
    const int k0 = blockIdx.y * (FIN / SK);
    const int t  = threadIdx.x;
    const int c  = t & 127, rg = t >> 7;
    float acc[8];
#pragma unroll
    for (int r = 0; r < 8; r++) acc[r] = 0.0f;
    for (int kb = 0; kb < FIN / SK; kb += 32) {
        {
            int kk = t & 31, r = t >> 5;
#pragma unroll
            for (int i = 0; i < 2; i++) {
                int rr = r + i * 8, grow = rb + rr;
                As[rr][kk] = (grow < ND) ? dF[(size_t)grow * FIN + k0 + kb + kk] : 0.0f;
            }
        }
#pragma unroll
        for (int i = 0; i < 16; i++) {
            int lin = t + i * 256, kk = lin >> 7, cc = lin & 127;
            Bs[kk][cc] = W1[(size_t)(k0 + kb + kk) * DD + cc];
        }
        __syncthreads();
#pragma unroll 8
        for (int kk = 0; kk < 32; kk++) {
            float b = Bs[kk][c];
#pragma unroll
            for (int rr = 0; rr < 8; rr++) acc[rr] += As[rg * 8 + rr][kk] * b;
        }
        __syncthreads();
    }
#pragma unroll
    for (int rr = 0; rr < 8; rr++) {
        int grow = rb + rg * 8 + rr;
        if (grow < ND) atomicAdd(&g_h1[grow * DD + c], acc[rr]);
    }
}

// ---------------- K2: h = relu(relu(h1+b1) @ W2 + b2) ----------------
__global__ void k_mlp2(const float* __restrict__ W2, const float* __restrict__ b1,
                       const float* __restrict__ b2) {
    __shared__ float hs[8][128];
    const int rb = blockIdx.x * 8;
    const int t  = threadIdx.x;
#pragma unroll
    for (int i = 0; i < 4; i++) {
        int lin = t + i * 256, r = lin >> 7, cc = lin & 127;
        hs[r][cc] = fmaxf(g_h1[(rb + r) * DD + cc] + b1[cc], 0.0f);
    }
    __syncthreads();
    const int c = t & 127, rg = t >> 7;
    float acc[4];
#pragma unroll
    for (int rr = 0; rr < 4; rr++) acc[rr] = b2[c];
#pragma unroll 4
    for (int k = 0; k < 128; k++) {
        float w = W2[k * DD + c];
#pragma unroll
        for (int rr = 0; rr < 4; rr++) acc[rr] += hs[rg * 4 + rr][k] * w;
    }
#pragma unroll
    for (int rr = 0; rr < 4; rr++)
        g_h[(rb + rg * 4 + rr) * DD + c] = fmaxf(acc[rr], 0.0f);
}

// ---------------- K3: edge aggregation (only dst < ND matters) ----------------
__global__ void k_agg(const int* __restrict__ ei, const float* __restrict__ pe, int E) {
    const int e = blockIdx.x * 256 + threadIdx.x;
    const int lane = threadIdx.x & 31;
    int dst = 0, src = 0;
    bool act = false;
    if (e < E) {
        dst = ei[E + e];
        act = (dst < ND);
        if (act) src = ei[e];
    }
    unsigned m = __ballot_sync(0xffffffffu, act);
    while (m) {
        int leader = __ffs(m) - 1;
        m &= m - 1;
        int d = __shfl_sync(0xffffffffu, dst, leader);
        int s = __shfl_sync(0xffffffffu, src, leader);
        const float4* p = (s < ND) ? (const float4*)(g_h + s * DD)
                                   : (const float4*)(pe + (size_t)(s - ND) * DD);
        float4 v = p[lane];
        float* ap = g_agg + d * DD + lane * 4;
        asm volatile("red.global.add.v4.f32 [%0], {%1,%2,%3,%4};"
                     :: "l"(ap), "f"(v.x), "f"(v.y), "f"(v.z), "f"(v.w) : "memory");
        if (lane == 0) atomicAdd(&g_cnt[d], 1.0f);
    }
}

// ---------------- K4: finalX = relu(mean @ Wl + bl + h @ Wr), fp32 ----------
__global__ void k_sage(const float* __restrict__ Wl, const float* __restrict__ bl,
                       const float* __restrict__ Wr) {
    __shared__ float ms[8][128];
    __shared__ float hs[8][128];
    const int rb = blockIdx.x * 8;
    const int t  = threadIdx.x;
#pragma unroll
    for (int i = 0; i < 4; i++) {
        int lin = t + i * 256, r = lin >> 7, cc = lin & 127;
        float cnt = fmaxf(g_cnt[rb + r], 1.0f);
        ms[r][cc] = g_agg[(rb + r) * DD + cc] / cnt;
        hs[r][cc] = g_h[(rb + r) * DD + cc];
    }
    __syncthreads();
    const int c = t & 127, rg = t >> 7;
    float acc[4];
#pragma unroll
    for (int rr = 0; rr < 4; rr++) acc[rr] = bl[c];
#pragma unroll 4
    for (int k = 0; k < 128; k++) {
        float wl = Wl[k * DD + c];
        float wr = Wr[k * DD + c];
#pragma unroll
        for (int rr = 0; rr < 4; rr++)
            acc[rr] += ms[rg * 4 + rr][k] * wl + hs[rg * 4 + rr][k] * wr;
    }
#pragma unroll
    for (int rr = 0; rr < 4; rr++)
        g_fx[(rb + rg * 4 + rr) * DD + c] = fmaxf(acc[rr], 0.0f);
}

// ---------------- K5: U = oW1 @ oW2sel  (256x512, K=128) --------------------
// grid (8, 4): M tiles of 32 (rows of oW1), N tiles of 128 (selected cols)
__global__ void k_u(const float* __restrict__ oW1, const float* __restrict__ oW2,
                    const int* __restrict__ ses, int S, int nSe) {
    __shared__ float As[32][33];
    __shared__ float Bs[32][128];
    __shared__ int   sess[128];
    const int m0 = blockIdx.x * 32;
    const int n0 = blockIdx.y * 128;
    const int t  = threadIdx.x;
    if (t < 128) {
        int sn = n0 + t;
        sess[t] = (sn < S) ? ses[sn] : 0;
    }
    __syncthreads();
    const int c = t & 127, rg = t >> 7;
    float acc[16];
#pragma unroll
    for (int r = 0; r < 16; r++) acc[r] = 0.0f;
    for (int kb = 0; kb < DD; kb += 32) {
#pragma unroll
        for (int i = 0; i < 4; i++) {
            int lin = t + i * 256, r = lin >> 5, kk = lin & 31;
            As[r][kk] = oW1[(size_t)(m0 + r) * DD + kb + kk];
        }
#pragma unroll
        for (int i = 0; i < 16; i++) {
            int lin = t + i * 256, kk = lin >> 7, cc = lin & 127;
            Bs[kk][cc] = oW2[(size_t)(kb + kk) * nSe + sess[cc]];
        }
        __syncthreads();
#pragma unroll 8
        for (int kk = 0; kk < 32; kk++) {
            float b = Bs[kk][c];
#pragma unroll
            for (int rr = 0; rr < 16; rr++) acc[rr] += As[rg * 16 + rr][kk] * b;
        }
        __syncthreads();
    }
#pragma unroll
    for (int rr = 0; rr < 16; rr++)
        g_U[(size_t)(m0 + rg * 16 + rr) * 512 + n0 + c] = acc[rr];
}

// ---------------- K6: c = oB1 @ oW2sel + oB2sel ------------------------------
__global__ void k_c(const float* __restrict__ oB1, const float* __restrict__ oW2,
                    const float* __restrict__ oB2, const int* __restrict__ ses,
                    int S, int nSe) {
    int s = blockIdx.x * 256 + threadIdx.x;
    if (s >= 512) return;
    if (s >= S) { g_c[s] = 0.0f; return; }
    int idx = ses[s];
    float acc = oB2[idx];
#pragma unroll 4
    for (int d = 0; d < DD; d++)
        acc += oB1[d] * oW2[(size_t)d * nSe + idx];
    g_c[s] = acc;
}

// ---------------- K7: R = fx @ U[0:128] + c ;  S = fx @ U[128:256] -----------
// grid (16, 4, 2): M tiles 64 (fx rows), N tiles 128, z selects R/S
__global__ void k_rs() {
    __shared__ float As[64][33];
    __shared__ float Bs[32][128];
    const int m0 = blockIdx.x * 64;
    const int n0 = blockIdx.y * 128;
    const int z  = blockIdx.z;
    const int t  = threadIdx.x;
    const int c  = t & 127, rg = t >> 7;
    float acc[32];
#pragma unroll
    for (int r = 0; r < 32; r++) acc[r] = 0.0f;
    for (int kb = 0; kb < DD; kb += 32) {
#pragma unroll
        for (int i = 0; i < 8; i++) {
            int lin = t + i * 256, r = lin >> 5, kk = lin & 31;
            int row = m0 + r;
            As[r][kk] = (row < ND) ? g_fx[(size_t)row * DD + kb + kk] : 0.0f;
        }
#pragma unroll
        for (int i = 0; i < 16; i++) {
            int lin = t + i * 256, kk = lin >> 7, cc = lin & 127;
            Bs[kk][cc] = g_U[(size_t)(z * 128 + kb + kk) * 512 + n0 + cc];
        }
        __syncthreads();
#pragma unroll 8
        for (int kk = 0; kk < 32; kk++) {
            float b = Bs[kk][c];
#pragma unroll
            for (int rr = 0; rr < 32; rr++) acc[rr] += As[rg * 32 + rr][kk] * b;
        }
        __syncthreads();
    }
    float cadd = (z == 0) ? g_c[n0 + c] : 0.0f;
    float* dst = z ? g_S : g_R;
#pragma unroll
    for (int rr = 0; rr < 32; rr++) {
        int row = m0 + rg * 32 + rr;
        if (row < ND) dst[(size_t)row * 512 + n0 + c] = acc[rr] + cadd;
    }
}

// ---------------- K8: out[t,s] = R[i_t,s] + S[j_t,s]  (streamed) -------------
__global__ void __launch_bounds__(256)
k_out2(const int* __restrict__ tpl, float* __restrict__ out, int T, int S) {
    const int t = threadIdx.x;
    const int r = t >> 7, c = t & 127;
    const int m = blockIdx.x * 2 + r;
    if (m >= T || c >= 125) return;
    const int i = __ldg(&tpl[m * 2]);
    const int j = __ldg(&tpl[m * 2 + 1]);
    float4 a = __ldg((const float4*)(g_R + (size_t)i * 512) + c);
    float4 b = __ldg((const float4*)(g_S + (size_t)j * 512) + c);
    float4 o = { a.x + b.x, a.y + b.y, a.z + b.z, a.w + b.w };
    __stcs((float4*)(out + (size_t)m * S) + c, o);
}

// ---------------- host ----------------
extern "C" void kernel_launch(void* const* d_in, const int* in_sizes, int n_in,
                              void* d_out, int out_size) {
    const float* drugF = (const float*)d_in[0];
    const int*   ei    = (const int*)d_in[1];
    const int*   tpl   = (const int*)d_in[2];
    const int*   ses   = (const int*)d_in[3];
    const float* W1    = (const float*)d_in[4];
    const float* b1    = (const float*)d_in[5];
    const float* W2    = (const float*)d_in[6];
    const float* b2    = (const float*)d_in[7];
    const float* pe    = (const float*)d_in[8];
    const float* Wl    = (const float*)d_in[9];
    const float* bl    = (const float*)d_in[10];
    const float* Wr    = (const float*)d_in[11];
    const float* oW1   = (const float*)d_in[12];
    const float* oB1   = (const float*)d_in[13];
    const float* oW2   = (const float*)d_in[14];
    const float* oB2   = (const float*)d_in[15];

    const int E   = in_sizes[1] / 2;
    const int T   = in_sizes[2] / 2;
    const int S   = in_sizes[3];
    const int nSe = in_sizes[15];
    float* out = (float*)d_out;

    k_zero <<<(ND * DD + 255) / 256, 256>>>();
    k_mlp1 <<<dim3((ND + 15) / 16, SK), 256>>>(drugF, W1);
    k_u    <<<dim3(8, 4), 256>>>(oW1, oW2, ses, S, nSe);
    k_c    <<<2, 256>>>(oB1, oW2, oB2, ses, S, nSe);
    k_mlp2 <<<ND / 8, 256>>>(W2, b1, b2);
    k_agg  <<<(E + 255) / 256, 256>>>(ei, pe, E);
    k_sage <<<ND / 8, 256>>>(Wl, bl, Wr);
    k_rs   <<<dim3(16, 4, 2), 256>>>();
    k_out2 <<<(T + 1) / 2, 256>>>(tpl, out, T, S);
}